// round 14
// baseline (speedup 1.0000x reference)
#include <cuda_runtime.h>
#include <cuda_fp16.h>
#include <cstdint>

// ---------------------------------------------------------------------------
// LigEdgeBuilder: edge_attr = lig_ea + emb(d),  d = |pos[dst]-pos[src]|
// emb(d) precomputed as 1-D fp16 table (h=1/128, fp32 math) in global mem.
// Coalescing-first layout + phase-1 software pipelining:
//   phase 1 (pipelined 1 tile ahead): lane L owns edge e0+L -> endpoints, d
//   phase 2: stream 2 edges/instruction: lane L covers edge 2k+(L>>4),
//            cols (L&15)*4 -> lig/out accesses contiguous 512B/instr.
// ---------------------------------------------------------------------------

#define TROWS  4420
#define INVH   128.0f
#define THREADS 256
#define WARPS_PB (THREADS / 32)

__device__ __half g_table[TROWS * 64];

// ---- table builder: one block per d-row, 64 threads (one per column) ----
__global__ void build_table(const float* __restrict__ W1,
                            const float* __restrict__ b1,
                            const float* __restrict__ W2,
                            const float* __restrict__ b2)
{
    __shared__ float gg[50];
    __shared__ float hh[64];
    const int row = blockIdx.x;
    const int j   = threadIdx.x;
    const float d = (float)row * (1.0f / INVH);
    const float step  = 30.0f / 49.0f;
    const float coeff = -0.5f / (step * step);

    if (j < 50) {
        float t = d - (float)j * step;
        gg[j] = expf(coeff * t * t);
    }
    __syncthreads();

    float acc = b1[j];
#pragma unroll 10
    for (int r = 0; r < 50; r++) acc = fmaf(gg[r], W1[r * 64 + j], acc);
    hh[j] = fmaxf(acc, 0.0f);
    __syncthreads();

    float acc2 = b2[j];
#pragma unroll 16
    for (int k = 0; k < 64; k++) acc2 = fmaf(hh[k], W2[k * 64 + j], acc2);
    g_table[row * 64 + j] = __float2half(acc2);
}

__global__ void __launch_bounds__(THREADS)
lig_edge_kernel(const float* __restrict__ pos,
                const float* __restrict__ lig_ea,
                const void*  __restrict__ ei_raw,
                float* __restrict__ outAttr,
                float* __restrict__ outIdxF,   // nullable: fused idx->float out
                int E, int numTiles)
{
    const int tid  = threadIdx.x;
    const int lane = tid & 31;
    const int warp = tid >> 5;

    const long long* ei64 = (const long long*)ei_raw;
    const int*       ei32 = (const int*)ei_raw;

    // ---- edge_index dtype detection (per warp, once) ----
    int idx64;
    {
        long long v = 0;
        if (lane < 16 && lane < E) v = ei64[lane];
        int ok = (v >= 0 && v < (1LL << 31));
        idx64 = __all_sync(0xffffffffu, ok) ? 1 : 0;
    }
    const bool writeIdx = (outIdxF != nullptr);

    const int gwarp      = blockIdx.x * WARPS_PB + warp;
    const int totalWarps = gridDim.x * WARPS_PB;

    int tile = gwarp;

    // ---- pipeline prologue: phase-1 loads for the first tile ----
    float xs = 0.f, ys = 0.f, zs = 0.f, xd = 0.f, yd = 0.f, zd = 0.f;
    if (tile < numTiles) {
        const int eL = tile * 32 + lane;
        int srcI = 0, dstI = 0;
        if (eL < E) {
            if (idx64) { srcI = (int)ei64[eL]; dstI = (int)ei64[E + eL]; }
            else       { srcI = ei32[eL];      dstI = ei32[E + eL]; }
            if (writeIdx) {
                __stcs(outIdxF + eL,     (float)srcI);
                __stcs(outIdxF + E + eL, (float)dstI);
            }
        }
        const float* ps = pos + (unsigned)srcI * 3u;
        const float* pd = pos + (unsigned)dstI * 3u;
        xs = __ldg(ps + 0); ys = __ldg(ps + 1); zs = __ldg(ps + 2);
        xd = __ldg(pd + 0); yd = __ldg(pd + 1); zd = __ldg(pd + 2);
    }

    for (; tile < numTiles; tile += totalWarps) {
        const int e0 = tile * 32;

        // ---- finish phase 1 for CURRENT tile (loads issued last iter) ----
        float dx = xd - xs, dy = yd - ys, dz = zd - zs;
        float d  = sqrtf(dx * dx + dy * dy + dz * dz);
        float tt = fminf(d * INVH, (float)(TROWS - 2));

        // ---- issue phase-1 loads for NEXT tile (hidden under phase 2) ----
        const int nt = tile + totalWarps;
        if (nt < numTiles) {
            const int eL = nt * 32 + lane;
            int srcI = 0, dstI = 0;
            if (eL < E) {
                if (idx64) { srcI = (int)ei64[eL]; dstI = (int)ei64[E + eL]; }
                else       { srcI = ei32[eL];      dstI = ei32[E + eL]; }
                if (writeIdx) {
                    __stcs(outIdxF + eL,     (float)srcI);
                    __stcs(outIdxF + E + eL, (float)dstI);
                }
            }
            const float* ps = pos + (unsigned)srcI * 3u;
            const float* pd = pos + (unsigned)dstI * 3u;
            xs = __ldg(ps + 0); ys = __ldg(ps + 1); zs = __ldg(ps + 2);
            xd = __ldg(pd + 0); yd = __ldg(pd + 1); zd = __ldg(pd + 2);
        }

        // ---- phase 2: stream 2 edges per instruction, fully coalesced ----
        const int hlane = lane >> 4;         // which of the 2 edges this lane serves
        const int clane = lane & 15;         // 16B chunk within the edge row
        const float4* lp = (const float4*)lig_ea + (unsigned)e0 * 16u;
        float4*       op = (float4*)outAttr + (unsigned)e0 * 16u;
        const char* tbase = (const char*)g_table;

#pragma unroll 4
        for (int k = 0; k < 16; k++) {
            const int esel = 2 * k + hlane;              // local edge 0..31
            const float ts = __shfl_sync(0xffffffffu, tt, esel);
            const bool  vk = (e0 + esel < E);
            int   i0 = (int)ts;
            float fr = ts - (float)i0;
            // two adjacent table rows, 8B per lane, contiguous across lanes
            const uint2* tp = (const uint2*)(tbase + (unsigned)i0 * 128u + clane * 8);
            uint2 ta = __ldg(tp);
            uint2 tb = __ldg(tp + 16);                   // +128B = next row
            if (vk) {
                float4 lg = __ldcs(lp + k * 32 + lane);
                float2 a0 = __half22float2(*(const __half2*)&ta.x);
                float2 a1 = __half22float2(*(const __half2*)&ta.y);
                float2 b0 = __half22float2(*(const __half2*)&tb.x);
                float2 b1 = __half22float2(*(const __half2*)&tb.y);
                float4 r;
                r.x = lg.x + fmaf(fr, b0.x - a0.x, a0.x);
                r.y = lg.y + fmaf(fr, b0.y - a0.y, a0.y);
                r.z = lg.z + fmaf(fr, b1.x - a1.x, a1.x);
                r.w = lg.w + fmaf(fr, b1.y - a1.y, a1.y);
                __stcs(op + k * 32 + lane, r);
            }
        }
    }
}

// ---- fallback edge_index output (raw int64 path only) --------------------
__device__ __forceinline__ int detect64(const void* ei, int E) {
    const long long* p = (const long long*)ei;
    int ok = 1;
    int n = E < 16 ? E : 16;
    for (int i = 0; i < n; i++) {
        long long v = p[i];
        if (v < 0 || v >= (1LL << 31)) { ok = 0; break; }
    }
    return ok;
}

__global__ void write_idx_raw(const void* __restrict__ ei, long long* __restrict__ out,
                              int n, int E) {
    int i = blockIdx.x * blockDim.x + threadIdx.x;
    if (i < n) {
        int is64 = detect64(ei, E);
        long long v = is64 ? ((const long long*)ei)[i] : (long long)((const int*)ei)[i];
        out[i] = v;
    }
}

extern "C" void kernel_launch(void* const* d_in, const int* in_sizes, int n_in,
                              void* d_out, int out_size)
{
    const float* pos = nullptr;
    const float* lig = nullptr;
    const void*  ei  = nullptr;
    const float* W1  = nullptr;
    const float* b1  = nullptr;
    const float* W2  = nullptr;
    const float* b2  = nullptr;

    long long maxSz = -1; int ligIdx = -1;
    for (int i = 0; i < n_in; i++)
        if ((long long)in_sizes[i] > maxSz) { maxSz = in_sizes[i]; ligIdx = i; }
    lig = (const float*)d_in[ligIdx];
    const int E = (int)(maxSz / 64);

    for (int i = 0; i < n_in; i++) {
        long long sz = in_sizes[i];
        if (i == ligIdx) continue;
        if (sz == 50LL * 64)          W1 = (const float*)d_in[i];
        else if (sz == 64LL * 64)     W2 = (const float*)d_in[i];
        else if (sz == 64) {
            if (!b1) b1 = (const float*)d_in[i];
            else     b2 = (const float*)d_in[i];
        }
        else if (sz == 2LL * E || sz == 4LL * E) ei = d_in[i];
        else                        pos = (const float*)d_in[i];
    }

    float* out   = (float*)d_out;
    float* attr  = out;
    float* idxF  = nullptr;
    const long long nAttr = (long long)E * 64;

    if ((long long)out_size == nAttr + 2LL * E) {
        idxF = out;                 // fused into main kernel
        attr = out + 2LL * E;
    } else if ((long long)out_size == nAttr + 4LL * E) {
        int n = 2 * E;
        write_idx_raw<<<(n + 255) / 256, 256>>>(ei, (long long*)d_out, n, E);
        attr = out + 4LL * E;
    }

    // 1) build the emb(d) table (fp32 math, fp16 storage), ~5us
    build_table<<<TROWS, 64>>>(W1, b1, W2, b2);

    // 2) streaming main kernel (persistent grid-stride, capped)
    const int numTiles = (E + 31) / 32;
    int grid = (numTiles + WARPS_PB - 1) / WARPS_PB;
    if (grid > 888) grid = 888;   // 148 SMs * 6 CTAs, grid-stride persistent
    lig_edge_kernel<<<grid, THREADS>>>(pos, lig, ei, attr, idxF, E, numTiles);
}

// round 16
// speedup vs baseline: 1.0549x; 1.0549x over previous
#include <cuda_runtime.h>
#include <cuda_fp16.h>
#include <cstdint>

// ---------------------------------------------------------------------------
// LigEdgeBuilder: edge_attr = lig_ea + emb(d),  d = |pos[dst]-pos[src]|
// emb(d) precomputed as 1-D fp16 table (h=1/128, fp32 math) in global mem.
// Coalescing-first layout, max-occupancy build (32 regs, 8 CTAs/SM = 2048 thr):
//   phase 1: lane L owns edge e0+L -> both endpoints, d, table coord tt
//   phase 2: stream 2 edges/instruction: lane L covers edge 2k+(L>>4),
//            cols (L&15)*4 -> lig/out accesses contiguous 512B/instr.
// ---------------------------------------------------------------------------

#define TROWS  4420
#define INVH   128.0f
#define THREADS 256
#define WARPS_PB (THREADS / 32)

__device__ __half g_table[TROWS * 64];

// ---- table builder: one block per d-row, 64 threads (one per column) ----
__global__ void build_table(const float* __restrict__ W1,
                            const float* __restrict__ b1,
                            const float* __restrict__ W2,
                            const float* __restrict__ b2)
{
    __shared__ float gg[50];
    __shared__ float hh[64];
    const int row = blockIdx.x;
    const int j   = threadIdx.x;
    const float d = (float)row * (1.0f / INVH);
    const float step  = 30.0f / 49.0f;
    const float coeff = -0.5f / (step * step);

    if (j < 50) {
        float t = d - (float)j * step;
        gg[j] = expf(coeff * t * t);
    }
    __syncthreads();

    float acc = b1[j];
#pragma unroll 10
    for (int r = 0; r < 50; r++) acc = fmaf(gg[r], W1[r * 64 + j], acc);
    hh[j] = fmaxf(acc, 0.0f);
    __syncthreads();

    float acc2 = b2[j];
#pragma unroll 16
    for (int k = 0; k < 64; k++) acc2 = fmaf(hh[k], W2[k * 64 + j], acc2);
    g_table[row * 64 + j] = __float2half(acc2);
}

__global__ void __launch_bounds__(THREADS, 8)
lig_edge_kernel(const float* __restrict__ pos,
                const float* __restrict__ lig_ea,
                const void*  __restrict__ ei_raw,
                float* __restrict__ outAttr,
                float* __restrict__ outIdxF,   // nullable: fused idx->float out
                int E, int numTiles)
{
    const int tid  = threadIdx.x;
    const int lane = tid & 31;
    const int warp = tid >> 5;

    const long long* ei64 = (const long long*)ei_raw;
    const int*       ei32 = (const int*)ei_raw;

    // ---- edge_index dtype detection (per warp, once) ----
    int idx64;
    {
        long long v = 0;
        if (lane < 16 && lane < E) v = ei64[lane];
        int ok = (v >= 0 && v < (1LL << 31));
        idx64 = __all_sync(0xffffffffu, ok) ? 1 : 0;
    }
    const bool writeIdx = (outIdxF != nullptr);

    const int gwarp      = blockIdx.x * WARPS_PB + warp;
    const int totalWarps = gridDim.x * WARPS_PB;

    for (int tile = gwarp; tile < numTiles; tile += totalWarps) {
        const int e0 = tile * 32;

        // ---- phase 1: lane L owns edge e0+L -> d and table coordinate ----
        const int  eL = e0 + lane;
        const bool vL = (eL < E);
        int srcI = 0, dstI = 0;
        if (vL) {
            if (idx64) { srcI = (int)ei64[eL]; dstI = (int)ei64[E + eL]; }
            else       { srcI = ei32[eL];      dstI = ei32[E + eL]; }
        }
        if (writeIdx && vL) {                      // fused idx float output
            __stcs(outIdxF + eL,     (float)srcI);
            __stcs(outIdxF + E + eL, (float)dstI);
        }
        const float* ps = pos + (unsigned)srcI * 3u;
        const float* pd = pos + (unsigned)dstI * 3u;
        float dx = __ldg(pd + 0) - __ldg(ps + 0);
        float dy = __ldg(pd + 1) - __ldg(ps + 1);
        float dz = __ldg(pd + 2) - __ldg(ps + 2);
        float d  = sqrtf(dx * dx + dy * dy + dz * dz);
        float tt = fminf(d * INVH, (float)(TROWS - 2));

        // ---- phase 2: stream 2 edges per instruction, fully coalesced ----
        const int hlane = lane >> 4;         // which of the 2 edges this lane serves
        const int clane = lane & 15;         // 16B chunk within the edge row
        const float4* lp = (const float4*)lig_ea + (unsigned)e0 * 16u;
        float4*       op = (float4*)outAttr + (unsigned)e0 * 16u;
        const char* tbase = (const char*)g_table;

#pragma unroll 4
        for (int k = 0; k < 16; k++) {
            const int esel = 2 * k + hlane;              // local edge 0..31
            const float ts = __shfl_sync(0xffffffffu, tt, esel);
            const bool  vk = (e0 + esel < E);
            int   i0 = (int)ts;
            float fr = ts - (float)i0;
            // two adjacent table rows, 8B per lane, contiguous across lanes
            const uint2* tp = (const uint2*)(tbase + (unsigned)i0 * 128u + clane * 8);
            uint2 ta = __ldg(tp);
            uint2 tb = __ldg(tp + 16);                   // +128B = next row
            if (vk) {
                float4 lg = __ldcs(lp + k * 32 + lane);
                float2 a0 = __half22float2(*(const __half2*)&ta.x);
                float2 a1 = __half22float2(*(const __half2*)&ta.y);
                float2 b0 = __half22float2(*(const __half2*)&tb.x);
                float2 b1 = __half22float2(*(const __half2*)&tb.y);
                float4 r;
                r.x = lg.x + fmaf(fr, b0.x - a0.x, a0.x);
                r.y = lg.y + fmaf(fr, b0.y - a0.y, a0.y);
                r.z = lg.z + fmaf(fr, b1.x - a1.x, a1.x);
                r.w = lg.w + fmaf(fr, b1.y - a1.y, a1.y);
                __stcs(op + k * 32 + lane, r);
            }
        }
    }
}

// ---- fallback edge_index output (raw int64 path only) --------------------
__device__ __forceinline__ int detect64(const void* ei, int E) {
    const long long* p = (const long long*)ei;
    int ok = 1;
    int n = E < 16 ? E : 16;
    for (int i = 0; i < n; i++) {
        long long v = p[i];
        if (v < 0 || v >= (1LL << 31)) { ok = 0; break; }
    }
    return ok;
}

__global__ void write_idx_raw(const void* __restrict__ ei, long long* __restrict__ out,
                              int n, int E) {
    int i = blockIdx.x * blockDim.x + threadIdx.x;
    if (i < n) {
        int is64 = detect64(ei, E);
        long long v = is64 ? ((const long long*)ei)[i] : (long long)((const int*)ei)[i];
        out[i] = v;
    }
}

extern "C" void kernel_launch(void* const* d_in, const int* in_sizes, int n_in,
                              void* d_out, int out_size)
{
    const float* pos = nullptr;
    const float* lig = nullptr;
    const void*  ei  = nullptr;
    const float* W1  = nullptr;
    const float* b1  = nullptr;
    const float* W2  = nullptr;
    const float* b2  = nullptr;

    long long maxSz = -1; int ligIdx = -1;
    for (int i = 0; i < n_in; i++)
        if ((long long)in_sizes[i] > maxSz) { maxSz = in_sizes[i]; ligIdx = i; }
    lig = (const float*)d_in[ligIdx];
    const int E = (int)(maxSz / 64);

    for (int i = 0; i < n_in; i++) {
        long long sz = in_sizes[i];
        if (i == ligIdx) continue;
        if (sz == 50LL * 64)          W1 = (const float*)d_in[i];
        else if (sz == 64LL * 64)     W2 = (const float*)d_in[i];
        else if (sz == 64) {
            if (!b1) b1 = (const float*)d_in[i];
            else     b2 = (const float*)d_in[i];
        }
        else if (sz == 2LL * E || sz == 4LL * E) ei = d_in[i];
        else                        pos = (const float*)d_in[i];
    }

    float* out   = (float*)d_out;
    float* attr  = out;
    float* idxF  = nullptr;
    const long long nAttr = (long long)E * 64;

    if ((long long)out_size == nAttr + 2LL * E) {
        idxF = out;                 // fused into main kernel
        attr = out + 2LL * E;
    } else if ((long long)out_size == nAttr + 4LL * E) {
        int n = 2 * E;
        write_idx_raw<<<(n + 255) / 256, 256>>>(ei, (long long*)d_out, n, E);
        attr = out + 4LL * E;
    }

    // 1) build the emb(d) table (fp32 math, fp16 storage), ~5us
    build_table<<<TROWS, 64>>>(W1, b1, W2, b2);

    // 2) streaming main kernel (persistent grid-stride, 8 CTAs/SM)
    const int numTiles = (E + 31) / 32;
    int grid = (numTiles + WARPS_PB - 1) / WARPS_PB;
    if (grid > 1184) grid = 1184;   // 148 SMs * 8 CTAs = 2048 threads/SM (max)
    lig_edge_kernel<<<grid, THREADS>>>(pos, lig, ei, attr, idxF, E, numTiles);
}